// round 6
// baseline (speedup 1.0000x reference)
#include <cuda_runtime.h>
#include <stdint.h>

#define B_MAX 16384
#define IPB 16   // images per block

// ---------------- weight scratch (device globals) ----------------
__device__ unsigned g_wp1[8];         // conv1 weight sign bits (25 per oc)
__device__ unsigned g_wp2[16 * 8];    // conv2 weights packed 150b -> 5 words, pad 8
__device__ unsigned g_fw1[120 * 16];  // fc1: 25-bit word per (n, oc)
__device__ unsigned g_fw2[84 * 4];    // fc2: 120 bits -> 4 words per n
__device__ unsigned g_fw3[10 * 3];    // fc3: 84 bits -> 3 words per n

// ---------------- K0: pack all weights into sign bitmasks ----------------
__global__ void pack_weights(const float* __restrict__ w1, const float* __restrict__ w2,
                             const float* __restrict__ f1, const float* __restrict__ f2,
                             const float* __restrict__ f3) {
    int t = blockIdx.x * blockDim.x + threadIdx.x;
    int stride = blockDim.x * gridDim.x;

    if (t < 8) {
        unsigned v = 0;
        if (t < 6)
            for (int i = 0; i < 25; i++) v |= (unsigned)(w1[t * 25 + i] > 0.f) << i;
        g_wp1[t] = v;
    }
    if (t < 16) {  // oc: pack 6x25 bits -> 5x32-bit dense words
        unsigned wi[6];
        for (int ic = 0; ic < 6; ic++) {
            unsigned v = 0;
            for (int i = 0; i < 25; i++) v |= (unsigned)(w2[(t * 6 + ic) * 25 + i] > 0.f) << i;
            wi[ic] = v;
        }
        g_wp2[t * 8 + 0] = wi[0] | (wi[1] << 25);
        g_wp2[t * 8 + 1] = (wi[1] >> 7) | (wi[2] << 18);
        g_wp2[t * 8 + 2] = (wi[2] >> 14) | (wi[3] << 11);
        g_wp2[t * 8 + 3] = (wi[3] >> 21) | (wi[4] << 4) | (wi[5] << 29);
        g_wp2[t * 8 + 4] = (wi[5] >> 3);
        g_wp2[t * 8 + 5] = 0; g_wp2[t * 8 + 6] = 0; g_wp2[t * 8 + 7] = 0;
    }
    for (int w = t; w < 120 * 16; w += stride) {
        int n = w >> 4, oc = w & 15;
        unsigned v = 0;
        for (int i = 0; i < 25; i++) v |= (unsigned)(f1[n * 400 + oc * 25 + i] > 0.f) << i;
        g_fw1[w] = v;
    }
    for (int w = t; w < 84 * 4; w += stride) {
        int n = w >> 2, j = w & 3;
        unsigned v = 0;
        for (int k = 0; k < 32; k++) {
            int i = j * 32 + k;
            if (i < 120) v |= (unsigned)(f2[n * 120 + i] > 0.f) << k;
        }
        g_fw2[w] = v;
    }
    for (int w = t; w < 10 * 3; w += stride) {
        int n = w / 3, j = w % 3;
        unsigned v = 0;
        for (int k = 0; k < 32; k++) {
            int i = j * 32 + k;
            if (i < 84) v |= (unsigned)(f3[n * 84 + i] > 0.f) << k;
        }
        g_fw3[w] = v;
    }
}

// ---------------- mega kernel: pack -> conv1 -> conv2 -> fc --------------
__global__ void __launch_bounds__(256, 4) mega_k(const float* __restrict__ x,
                                                 float* __restrict__ out, int B) {
    __shared__ unsigned sx[IPB][32];
    __shared__ __align__(16) unsigned sc1[IPB][14][6];
    __shared__ unsigned ss2[IPB][25];
    __shared__ unsigned s1w[120 * 17];
    __shared__ unsigned s2w[84 * 5];
    __shared__ unsigned s3w[30];
    __shared__ unsigned swp1[6];
    __shared__ uint4 sw4[16][2];

    int tid = threadIdx.x, warp = tid >> 5, lane = tid & 31;
    int b0 = blockIdx.x * IPB;
    int imax = B - b0; if (imax > IPB) imax = IPB;

    // ---- load weights into smem ----
    for (int i = tid; i < 120 * 16; i += 256) s1w[(i >> 4) * 17 + (i & 15)] = g_fw1[i];
    for (int i = tid; i < 84 * 4; i += 256) s2w[(i >> 2) * 5 + (i & 3)] = g_fw2[i];
    if (tid < 30) s3w[tid] = g_fw3[tid];
    if (tid >= 32 && tid < 38) swp1[tid - 32] = g_wp1[tid - 32];
    if (tid >= 64 && tid < 96) {
        int k = tid - 64;
        sw4[k >> 1][k & 1] = ((const uint4*)&g_wp2[(k >> 1) * 8])[k & 1];
    }

    // ---- stage 1: pack x signs ----
    // image = 32 rows = 8 groups of 4 rows; IPB*8 = 128 groups over 8 warps
    // => 16 iterations (FIX: was IPB/2 = 8, leaving half the images unpacked)
#pragma unroll
    for (int it = 0; it < IPB; it++) {
        int g = warp + it * 8;              // 0 .. IPB*8-1
        int img = g >> 3, grp = g & 7;
        bool ok = (img < imax);
        const float* p = x + (size_t)(b0 + img) * 1024 + grp * 128 + lane;
        float v0 = ok ? p[0]  : 0.f;
        float v1 = ok ? p[32] : 0.f;
        float v2 = ok ? p[64] : 0.f;
        float v3 = ok ? p[96] : 0.f;
        unsigned q0 = __ballot_sync(0xffffffffu, v0 > 0.f);
        unsigned q1 = __ballot_sync(0xffffffffu, v1 > 0.f);
        unsigned q2 = __ballot_sync(0xffffffffu, v2 > 0.f);
        unsigned q3 = __ballot_sync(0xffffffffu, v3 > 0.f);
        if (lane == 0 && ok) {
            sx[img][grp * 4 + 0] = q0; sx[img][grp * 4 + 1] = q1;
            sx[img][grp * 4 + 2] = q2; sx[img][grp * 4 + 3] = q3;
        }
    }
    __syncthreads();

    // ---- stage 2: conv1 + pool + binarize (IPB*14 cells) ----
    if (tid < imax * 14) {
        int img = tid / 14, py = tid % 14;
        unsigned r[6];
#pragma unroll
        for (int k = 0; k < 6; k++) r[k] = sx[img][2 * py + k];
        unsigned w[6];
#pragma unroll
        for (int oc = 0; oc < 6; oc++) w[oc] = swp1[oc];

        unsigned o[6] = {0, 0, 0, 0, 0, 0};
#pragma unroll
        for (int ox = 0; ox < 28; ox++) {
            unsigned win0 = 0;
#pragma unroll
            for (int j = 0; j < 5; j++) win0 |= ((r[j] >> ox) & 31u) << (5 * j);
            unsigned win1 = (win0 >> 5) | (((r[5] >> ox) & 31u) << 20);
            unsigned bit = 1u << (ox >> 1);
#pragma unroll
            for (int oc = 0; oc < 6; oc++) {
                int m = min(__popc(win0 ^ w[oc]), __popc(win1 ^ w[oc]));
                if (m <= 12) o[oc] |= bit;
            }
        }
#pragma unroll
        for (int oc = 0; oc < 6; oc++) sc1[img][py][oc] = o[oc];
    }
    __syncthreads();

    // ---- stage 3: conv2 + pool + ternarize (IPB*25 cells) ----
    for (int t = tid; t < imax * 25; t += 256) {
        int img = t / 25, cell = t % 25;
        int py = cell / 5, px = cell % 5;
        int ox0 = 2 * px;

        unsigned wpk[4][5];
#pragma unroll
        for (int q = 0; q < 4; q++)
#pragma unroll
            for (int w = 0; w < 5; w++) wpk[q][w] = 0u;

#pragma unroll
        for (int icp = 0; icp < 3; icp++) {
            unsigned ra[6], rb[6];
#pragma unroll
            for (int k = 0; k < 6; k++) {
                uint2 v = *(const uint2*)&sc1[img][2 * py + k][icp * 2];
                ra[k] = v.x; rb[k] = v.y;
            }
#pragma unroll
            for (int h = 0; h < 2; h++) {
                int ox = ox0 + h;
                unsigned va0 = 0, vb0 = 0;
#pragma unroll
                for (int j = 0; j < 5; j++) {
                    va0 |= ((ra[j] >> ox) & 31u) << (5 * j);
                    vb0 |= ((rb[j] >> ox) & 31u) << (5 * j);
                }
                unsigned va1 = (va0 >> 5) | (((ra[5] >> ox) & 31u) << 20);
                unsigned vb1 = (vb0 >> 5) | (((rb[5] >> ox) & 31u) << 20);
                if (icp == 0) {
                    wpk[h][0]     |= va0 | (vb0 << 25);
                    wpk[h][1]     |= vb0 >> 7;
                    wpk[2 + h][0] |= va1 | (vb1 << 25);
                    wpk[2 + h][1] |= vb1 >> 7;
                } else if (icp == 1) {
                    wpk[h][1]     |= va0 << 18;
                    wpk[h][2]     |= (va0 >> 14) | (vb0 << 11);
                    wpk[h][3]     |= vb0 >> 21;
                    wpk[2 + h][1] |= va1 << 18;
                    wpk[2 + h][2] |= (va1 >> 14) | (vb1 << 11);
                    wpk[2 + h][3] |= vb1 >> 21;
                } else {
                    wpk[h][3]     |= (va0 << 4) | (vb0 << 29);
                    wpk[h][4]     |= vb0 >> 3;
                    wpk[2 + h][3] |= (va1 << 4) | (vb1 << 29);
                    wpk[2 + h][4] |= vb1 >> 3;
                }
            }
        }

        unsigned word = 0;
#pragma unroll
        for (int oc = 0; oc < 16; oc++) {
            uint4 wa = sw4[oc][0];
            unsigned w4v = sw4[oc][1].x;
            int d0 = __popc(wpk[0][0] ^ wa.x) + __popc(wpk[0][1] ^ wa.y)
                   + __popc(wpk[0][2] ^ wa.z) + __popc(wpk[0][3] ^ wa.w)
                   + __popc(wpk[0][4] ^ w4v);
            int d1 = __popc(wpk[1][0] ^ wa.x) + __popc(wpk[1][1] ^ wa.y)
                   + __popc(wpk[1][2] ^ wa.z) + __popc(wpk[1][3] ^ wa.w)
                   + __popc(wpk[1][4] ^ w4v);
            int d2 = __popc(wpk[2][0] ^ wa.x) + __popc(wpk[2][1] ^ wa.y)
                   + __popc(wpk[2][2] ^ wa.z) + __popc(wpk[2][3] ^ wa.w)
                   + __popc(wpk[2][4] ^ w4v);
            int d3 = __popc(wpk[3][0] ^ wa.x) + __popc(wpk[3][1] ^ wa.y)
                   + __popc(wpk[3][2] ^ wa.z) + __popc(wpk[3][3] ^ wa.w)
                   + __popc(wpk[3][4] ^ w4v);
            int m = min(min(d0, d1), min(d2, d3));
            if (m <= 74) word |= 1u << oc;
            if (m != 75) word |= 1u << (16 + oc);
        }
        ss2[img][cell] = word;
    }
    __syncthreads();

    // ---- stage 4: fc1 -> fc2 -> fc3, one warp per image ----
#pragma unroll
    for (int it = 0; it < IPB / 8; it++) {
        int img = warp + it * 8;
        if (img >= imax) continue;   // uniform per warp

        unsigned W = (lane < 25) ? ss2[img][lane] : 0u;
        unsigned sp[16], sm[16];
#pragma unroll
        for (int oc = 0; oc < 16; oc++) {
            sp[oc] = __ballot_sync(0xffffffffu, (W >> oc) & 1u);
            sm[oc] = __ballot_sync(0xffffffffu, (W >> (16 + oc)) & 1u);
        }
        int M1 = 0;
#pragma unroll
        for (int i = 0; i < 16; i++) M1 += __popc(sm[i]);

        unsigned p2s[4], p2m[4];
#pragma unroll
        for (int k = 0; k < 4; k++) {
            int n = k * 32 + lane;
            int v = 0;
            bool valid = (n < 120);
            if (valid) {
                int p = 0;
#pragma unroll
                for (int i = 0; i < 16; i++)
                    p += __popc((~(sp[i] ^ s1w[n * 17 + i])) & sm[i]);
                v = 2 * p - M1;
            }
            p2s[k] = __ballot_sync(0xffffffffu, valid && (v > 0));
            p2m[k] = __ballot_sync(0xffffffffu, valid && (v != 0));
        }
        int M2 = __popc(p2m[0]) + __popc(p2m[1]) + __popc(p2m[2]) + __popc(p2m[3]);

        unsigned p3s[3], p3m[3];
#pragma unroll
        for (int k = 0; k < 3; k++) {
            int n = k * 32 + lane;
            int v = 0;
            bool valid = (n < 84);
            if (valid) {
                int p = 0;
#pragma unroll
                for (int j = 0; j < 4; j++)
                    p += __popc((~(p2s[j] ^ s2w[n * 5 + j])) & p2m[j]);
                v = 2 * p - M2;
            }
            p3s[k] = __ballot_sync(0xffffffffu, valid && (v > 0));
            p3m[k] = __ballot_sync(0xffffffffu, valid && (v != 0));
        }
        int M3 = __popc(p3m[0]) + __popc(p3m[1]) + __popc(p3m[2]);

        if (lane < 10) {
            int p = 0;
#pragma unroll
            for (int j = 0; j < 3; j++)
                p += __popc((~(p3s[j] ^ s3w[lane * 3 + j])) & p3m[j]);
            out[(size_t)(b0 + img) * 10 + lane] = (float)(2 * p - M3);
        }
    }
}

// ---------------- launch ----------------
extern "C" void kernel_launch(void* const* d_in, const int* in_sizes, int n_in,
                              void* d_out, int out_size) {
    const float* x  = (const float*)d_in[0];
    const float* w1 = (const float*)d_in[1];
    const float* w2 = (const float*)d_in[2];
    const float* f1 = (const float*)d_in[3];
    const float* f2 = (const float*)d_in[4];
    const float* f3 = (const float*)d_in[5];
    float* out = (float*)d_out;

    int B = in_sizes[0] / 1024;
    if (B > B_MAX) B = B_MAX;

    pack_weights<<<8, 256>>>(w1, w2, f1, f2, f3);

    int blocks = (B + IPB - 1) / IPB;
    mega_k<<<blocks, 256>>>(x, out, B);
}

// round 7
// speedup vs baseline: 1.0580x; 1.0580x over previous
#include <cuda_runtime.h>
#include <stdint.h>

#define B_MAX 16384
#define IPB 8   // images per block

// ---------------- weight scratch (device globals) ----------------
__device__ unsigned g_wp1[8];         // conv1 weight sign bits (25 per oc)
__device__ unsigned g_wp2[16 * 8];    // conv2 weights packed 150b -> 5 words, pad 8
__device__ unsigned g_fw1[120 * 16];  // fc1: 25-bit word per (n, oc)
__device__ unsigned g_fw2[84 * 4];    // fc2: 120 bits -> 4 words per n
__device__ unsigned g_fw3[10 * 3];    // fc3: 84 bits -> 3 words per n

// ---------------- K0: pack all weights into sign bitmasks ----------------
__global__ void pack_weights(const float* __restrict__ w1, const float* __restrict__ w2,
                             const float* __restrict__ f1, const float* __restrict__ f2,
                             const float* __restrict__ f3) {
    int t = blockIdx.x * blockDim.x + threadIdx.x;
    int stride = blockDim.x * gridDim.x;

    if (t < 8) {
        unsigned v = 0;
        if (t < 6)
            for (int i = 0; i < 25; i++) v |= (unsigned)(w1[t * 25 + i] > 0.f) << i;
        g_wp1[t] = v;
    }
    if (t < 16) {  // oc: pack 6x25 bits -> 5x32-bit dense words
        unsigned wi[6];
        for (int ic = 0; ic < 6; ic++) {
            unsigned v = 0;
            for (int i = 0; i < 25; i++) v |= (unsigned)(w2[(t * 6 + ic) * 25 + i] > 0.f) << i;
            wi[ic] = v;
        }
        g_wp2[t * 8 + 0] = wi[0] | (wi[1] << 25);
        g_wp2[t * 8 + 1] = (wi[1] >> 7) | (wi[2] << 18);
        g_wp2[t * 8 + 2] = (wi[2] >> 14) | (wi[3] << 11);
        g_wp2[t * 8 + 3] = (wi[3] >> 21) | (wi[4] << 4) | (wi[5] << 29);
        g_wp2[t * 8 + 4] = (wi[5] >> 3);
        g_wp2[t * 8 + 5] = 0; g_wp2[t * 8 + 6] = 0; g_wp2[t * 8 + 7] = 0;
    }
    for (int w = t; w < 120 * 16; w += stride) {
        int n = w >> 4, oc = w & 15;
        unsigned v = 0;
        for (int i = 0; i < 25; i++) v |= (unsigned)(f1[n * 400 + oc * 25 + i] > 0.f) << i;
        g_fw1[w] = v;
    }
    for (int w = t; w < 84 * 4; w += stride) {
        int n = w >> 2, j = w & 3;
        unsigned v = 0;
        for (int k = 0; k < 32; k++) {
            int i = j * 32 + k;
            if (i < 120) v |= (unsigned)(f2[n * 120 + i] > 0.f) << k;
        }
        g_fw2[w] = v;
    }
    for (int w = t; w < 10 * 3; w += stride) {
        int n = w / 3, j = w % 3;
        unsigned v = 0;
        for (int k = 0; k < 32; k++) {
            int i = j * 32 + k;
            if (i < 84) v |= (unsigned)(f3[n * 84 + i] > 0.f) << k;
        }
        g_fw3[w] = v;
    }
}

// ---------------- mega kernel: pack -> conv1 -> conv2 -> fc --------------
__global__ void __launch_bounds__(256, 5) mega_k(const float* __restrict__ x,
                                                 float* __restrict__ out, int B) {
    __shared__ unsigned sx[IPB][32];
    __shared__ __align__(16) unsigned sc1[IPB][14][6];
    __shared__ unsigned ss2[IPB][25];
    __shared__ unsigned s1w[120 * 17];
    __shared__ unsigned s2w[84 * 5];
    __shared__ unsigned s3w[30];
    __shared__ unsigned swp1[6];
    __shared__ uint4 sw4[16][2];

    int tid = threadIdx.x, warp = tid >> 5, lane = tid & 31;
    int b0 = blockIdx.x * IPB;
    int imax = B - b0; if (imax > IPB) imax = IPB;

    // ---- load weights into smem ----
    for (int i = tid; i < 120 * 16; i += 256) s1w[(i >> 4) * 17 + (i & 15)] = g_fw1[i];
    for (int i = tid; i < 84 * 4; i += 256) s2w[(i >> 2) * 5 + (i & 3)] = g_fw2[i];
    if (tid < 30) s3w[tid] = g_fw3[tid];
    if (tid >= 32 && tid < 38) swp1[tid - 32] = g_wp1[tid - 32];
    if (tid >= 64 && tid < 96) {
        int k = tid - 64;
        sw4[k >> 1][k & 1] = ((const uint4*)&g_wp2[(k >> 1) * 8])[k & 1];
    }

    // ---- stage 1: pack x signs ----
    // IPB*8 = 64 groups of 4 rows over 8 warps => 8 iterations
#pragma unroll
    for (int it = 0; it < IPB; it++) {
        int g = warp + it * 8;              // 0 .. IPB*8-1
        int img = g >> 3, grp = g & 7;
        bool ok = (img < imax);
        const float* p = x + (size_t)(b0 + img) * 1024 + grp * 128 + lane;
        float v0 = ok ? p[0]  : 0.f;
        float v1 = ok ? p[32] : 0.f;
        float v2 = ok ? p[64] : 0.f;
        float v3 = ok ? p[96] : 0.f;
        unsigned q0 = __ballot_sync(0xffffffffu, v0 > 0.f);
        unsigned q1 = __ballot_sync(0xffffffffu, v1 > 0.f);
        unsigned q2 = __ballot_sync(0xffffffffu, v2 > 0.f);
        unsigned q3 = __ballot_sync(0xffffffffu, v3 > 0.f);
        if (lane == 0 && ok) {
            sx[img][grp * 4 + 0] = q0; sx[img][grp * 4 + 1] = q1;
            sx[img][grp * 4 + 2] = q2; sx[img][grp * 4 + 3] = q3;
        }
    }
    __syncthreads();

    // ---- stage 2: conv1 + pool + binarize ----
    // IPB*14 rows, each split over 2 threads (half the 28 ox positions each);
    // halves merged with shfl_xor. 224 threads active (warps 0-6).
    if (tid < imax * 28) {
        int img = tid / 28, r = tid % 28;
        int py = r >> 1, h = r & 1;
        int oxlo = h * 14;

        unsigned rr[6];
#pragma unroll
        for (int k = 0; k < 6; k++) rr[k] = sx[img][2 * py + k];
        unsigned w[6];
#pragma unroll
        for (int oc = 0; oc < 6; oc++) w[oc] = swp1[oc];

        unsigned o[6] = {0, 0, 0, 0, 0, 0};
#pragma unroll
        for (int dx = 0; dx < 14; dx++) {
            int ox = oxlo + dx;
            unsigned win0 = 0;
#pragma unroll
            for (int j = 0; j < 5; j++) win0 |= ((rr[j] >> ox) & 31u) << (5 * j);
            unsigned win1 = (win0 >> 5) | (((rr[5] >> ox) & 31u) << 20);
            unsigned bit = 1u << (ox >> 1);
#pragma unroll
            for (int oc = 0; oc < 6; oc++) {
                int m = min(__popc(win0 ^ w[oc]), __popc(win1 ^ w[oc]));
                if (m <= 12) o[oc] |= bit;
            }
        }
        // merge the two halves (adjacent lanes, never straddle a warp)
#pragma unroll
        for (int oc = 0; oc < 6; oc++)
            o[oc] |= __shfl_xor_sync(0xffffffffu, o[oc], 1);
        if (h == 0) {
#pragma unroll
            for (int oc = 0; oc < 6; oc++) sc1[img][py][oc] = o[oc];
        }
    }
    __syncthreads();

    // ---- stage 3: conv2 + pool + ternarize (IPB*25 = 200 cells, 1 pass) --
    if (tid < imax * 25) {
        int img = tid / 25, cell = tid % 25;
        int py = cell / 5, px = cell % 5;
        int ox0 = 2 * px;

        unsigned wpk[4][5];
#pragma unroll
        for (int q = 0; q < 4; q++)
#pragma unroll
            for (int w = 0; w < 5; w++) wpk[q][w] = 0u;

#pragma unroll
        for (int icp = 0; icp < 3; icp++) {
            unsigned ra[6], rb[6];
#pragma unroll
            for (int k = 0; k < 6; k++) {
                uint2 v = *(const uint2*)&sc1[img][2 * py + k][icp * 2];
                ra[k] = v.x; rb[k] = v.y;
            }
#pragma unroll
            for (int h = 0; h < 2; h++) {
                int ox = ox0 + h;
                unsigned va0 = 0, vb0 = 0;
#pragma unroll
                for (int j = 0; j < 5; j++) {
                    va0 |= ((ra[j] >> ox) & 31u) << (5 * j);
                    vb0 |= ((rb[j] >> ox) & 31u) << (5 * j);
                }
                unsigned va1 = (va0 >> 5) | (((ra[5] >> ox) & 31u) << 20);
                unsigned vb1 = (vb0 >> 5) | (((rb[5] >> ox) & 31u) << 20);
                if (icp == 0) {
                    wpk[h][0]     |= va0 | (vb0 << 25);
                    wpk[h][1]     |= vb0 >> 7;
                    wpk[2 + h][0] |= va1 | (vb1 << 25);
                    wpk[2 + h][1] |= vb1 >> 7;
                } else if (icp == 1) {
                    wpk[h][1]     |= va0 << 18;
                    wpk[h][2]     |= (va0 >> 14) | (vb0 << 11);
                    wpk[h][3]     |= vb0 >> 21;
                    wpk[2 + h][1] |= va1 << 18;
                    wpk[2 + h][2] |= (va1 >> 14) | (vb1 << 11);
                    wpk[2 + h][3] |= vb1 >> 21;
                } else {
                    wpk[h][3]     |= (va0 << 4) | (vb0 << 29);
                    wpk[h][4]     |= vb0 >> 3;
                    wpk[2 + h][3] |= (va1 << 4) | (vb1 << 29);
                    wpk[2 + h][4] |= vb1 >> 3;
                }
            }
        }

        unsigned word = 0;
#pragma unroll
        for (int oc = 0; oc < 16; oc++) {
            uint4 wa = sw4[oc][0];
            unsigned w4v = sw4[oc][1].x;
            int d0 = __popc(wpk[0][0] ^ wa.x) + __popc(wpk[0][1] ^ wa.y)
                   + __popc(wpk[0][2] ^ wa.z) + __popc(wpk[0][3] ^ wa.w)
                   + __popc(wpk[0][4] ^ w4v);
            int d1 = __popc(wpk[1][0] ^ wa.x) + __popc(wpk[1][1] ^ wa.y)
                   + __popc(wpk[1][2] ^ wa.z) + __popc(wpk[1][3] ^ wa.w)
                   + __popc(wpk[1][4] ^ w4v);
            int d2 = __popc(wpk[2][0] ^ wa.x) + __popc(wpk[2][1] ^ wa.y)
                   + __popc(wpk[2][2] ^ wa.z) + __popc(wpk[2][3] ^ wa.w)
                   + __popc(wpk[2][4] ^ w4v);
            int d3 = __popc(wpk[3][0] ^ wa.x) + __popc(wpk[3][1] ^ wa.y)
                   + __popc(wpk[3][2] ^ wa.z) + __popc(wpk[3][3] ^ wa.w)
                   + __popc(wpk[3][4] ^ w4v);
            int m = min(min(d0, d1), min(d2, d3));
            if (m <= 74) word |= 1u << oc;
            if (m != 75) word |= 1u << (16 + oc);
        }
        ss2[img][cell] = word;
    }
    __syncthreads();

    // ---- stage 4: fc1 -> fc2 -> fc3, one warp per image (8 warps, 1 pass) -
    {
        int img = warp;
        if (img < imax) {
            unsigned W = (lane < 25) ? ss2[img][lane] : 0u;
            unsigned sp[16], sm[16];
#pragma unroll
            for (int oc = 0; oc < 16; oc++) {
                sp[oc] = __ballot_sync(0xffffffffu, (W >> oc) & 1u);
                sm[oc] = __ballot_sync(0xffffffffu, (W >> (16 + oc)) & 1u);
            }
            int M1 = 0;
#pragma unroll
            for (int i = 0; i < 16; i++) M1 += __popc(sm[i]);

            unsigned p2s[4], p2m[4];
#pragma unroll
            for (int k = 0; k < 4; k++) {
                int n = k * 32 + lane;
                int v = 0;
                bool valid = (n < 120);
                if (valid) {
                    int p = 0;
#pragma unroll
                    for (int i = 0; i < 16; i++)
                        p += __popc((~(sp[i] ^ s1w[n * 17 + i])) & sm[i]);
                    v = 2 * p - M1;
                }
                p2s[k] = __ballot_sync(0xffffffffu, valid && (v > 0));
                p2m[k] = __ballot_sync(0xffffffffu, valid && (v != 0));
            }
            int M2 = __popc(p2m[0]) + __popc(p2m[1]) + __popc(p2m[2]) + __popc(p2m[3]);

            unsigned p3s[3], p3m[3];
#pragma unroll
            for (int k = 0; k < 3; k++) {
                int n = k * 32 + lane;
                int v = 0;
                bool valid = (n < 84);
                if (valid) {
                    int p = 0;
#pragma unroll
                    for (int j = 0; j < 4; j++)
                        p += __popc((~(p2s[j] ^ s2w[n * 5 + j])) & p2m[j]);
                    v = 2 * p - M2;
                }
                p3s[k] = __ballot_sync(0xffffffffu, valid && (v > 0));
                p3m[k] = __ballot_sync(0xffffffffu, valid && (v != 0));
            }
            int M3 = __popc(p3m[0]) + __popc(p3m[1]) + __popc(p3m[2]);

            if (lane < 10) {
                int p = 0;
#pragma unroll
                for (int j = 0; j < 3; j++)
                    p += __popc((~(p3s[j] ^ s3w[lane * 3 + j])) & p3m[j]);
                out[(size_t)(b0 + img) * 10 + lane] = (float)(2 * p - M3);
            }
        }
    }
}

// ---------------- launch ----------------
extern "C" void kernel_launch(void* const* d_in, const int* in_sizes, int n_in,
                              void* d_out, int out_size) {
    const float* x  = (const float*)d_in[0];
    const float* w1 = (const float*)d_in[1];
    const float* w2 = (const float*)d_in[2];
    const float* f1 = (const float*)d_in[3];
    const float* f2 = (const float*)d_in[4];
    const float* f3 = (const float*)d_in[5];
    float* out = (float*)d_out;

    int B = in_sizes[0] / 1024;
    if (B > B_MAX) B = B_MAX;

    pack_weights<<<8, 256>>>(w1, w2, f1, f2, f3);

    int blocks = (B + IPB - 1) / IPB;
    mega_k<<<blocks, 256>>>(x, out, B);
}